// round 6
// baseline (speedup 1.0000x reference)
#include <cuda_runtime.h>

#define LN 1024
#define BATCH 64
#define THREADS 256
#define NCG 16
#define RPT 4
#define ROWS_PER_CTA 64
#define TILES (LN / ROWS_PER_CTA)
#define TOTAL_CTAS (BATCH * TILES)

typedef unsigned long long u64;

// Scratch (device globals; no runtime allocation).
__device__ ulonglong2 g_colA[BATCH][LN];  // ( pack(x0,y0), pack(x1,y1) )
__device__ ulonglong2 g_colB[BATCH][LN];  // ( pack(x2,y2), pack(sqx,sqy) )
__device__ float      g_msk[BATCH][LN];   // 1.0 if y-row observed else 0.0
__device__ float      g_part[TOTAL_CTAS];
__device__ int        g_ctr = 0;

// ---------- f32x2 helpers ----------
__device__ __forceinline__ u64 fma2(u64 a, u64 b, u64 c) {
    u64 d; asm("fma.rn.f32x2 %0, %1, %2, %3;" : "=l"(d) : "l"(a), "l"(b), "l"(c)); return d;
}
__device__ __forceinline__ u64 add2(u64 a, u64 b) {
    u64 d; asm("add.rn.f32x2 %0, %1, %2;" : "=l"(d) : "l"(a), "l"(b)); return d;
}
__device__ __forceinline__ u64 mul2(u64 a, u64 b) {
    u64 d; asm("mul.rn.f32x2 %0, %1, %2;" : "=l"(d) : "l"(a), "l"(b)); return d;
}
__device__ __forceinline__ u64 pack2(float lo, float hi) {
    u64 d; asm("mov.b64 %0, {%1, %2};" : "=l"(d) : "f"(lo), "f"(hi)); return d;
}
__device__ __forceinline__ float2 unpack2(u64 a) {
    float lo, hi; asm("mov.b64 {%0, %1}, %2;" : "=f"(lo), "=f"(hi) : "l"(a));
    return make_float2(lo, hi);
}
__device__ __forceinline__ float fast_sqrt(float a) {
    float r; asm("sqrt.approx.f32 %0, %1;" : "=f"(r) : "f"(a)); return r;
}

#define NEG2_PACKED 0xC0000000C0000000ULL  // (-2.0f, -2.0f)

// ---------- pre-kernel: pure transform, fully coalesced ----------
__global__ __launch_bounds__(THREADS)
void pre_kernel(const float* __restrict__ x, const float* __restrict__ y) {
    const int tid = threadIdx.x;
    const int b  = tid & (BATCH - 1);
    const int dl = tid >> 6;
    const int l  = blockIdx.x * 4 + dl;
    const int base = (l * BATCH + b) * 3;

    float x0 = x[base], x1 = x[base + 1], x2 = x[base + 2];
    float y0 = y[base], y1 = y[base + 1], y2 = y[base + 2];
    float sqx = fmaf(x2, x2, fmaf(x1, x1, x0 * x0));
    float sqy = fmaf(y2, y2, fmaf(y1, y1, y0 * y0));
    float m = ((y0 + y1 + y2) != 0.0f) ? 1.0f : 0.0f;

    ulonglong2 qa, qb;
    qa.x = pack2(x0, y0); qa.y = pack2(x1, y1);
    qb.x = pack2(x2, y2); qb.y = pack2(sqx, sqy);
    g_colA[b][l] = qa;
    g_colB[b][l] = qb;
    g_msk[b][l]  = m;
}

// ---------- pair kernel ----------
__global__ __launch_bounds__(THREADS, 5)
void pair_kernel(float* __restrict__ out) {
    const int b = blockIdx.x, tile = blockIdx.y, tid = threadIdx.x;
    const int warp = tid >> 5, lane = tid & 31;

    __shared__ ulonglong2 sA[LN];
    __shared__ ulonglong2 sB[LN];
    __shared__ float smsk[LN];
    __shared__ float s_red[8][9];
    __shared__ u64   s_hdr[4];
    __shared__ float s_nvf;
    __shared__ float wsum[8];
    __shared__ int   s_last;

    // ---- fill smem (coalesced 16B loads) + masked header sums ----
    float s[9] = {0, 0, 0, 0, 0, 0, 0, 0, 0};
#pragma unroll
    for (int i = tid; i < LN; i += THREADS) {
        ulonglong2 qa = g_colA[b][i];
        ulonglong2 qb = g_colB[b][i];
        float m = g_msk[b][i];
        sA[i] = qa; sB[i] = qb; smsk[i] = m;
        float2 p0 = unpack2(qa.x), p1 = unpack2(qa.y);
        float2 p2 = unpack2(qb.x), pq = unpack2(qb.y);
        s[0] = fmaf(m, p0.x, s[0]); s[1] = fmaf(m, p0.y, s[1]);
        s[2] = fmaf(m, p1.x, s[2]); s[3] = fmaf(m, p1.y, s[3]);
        s[4] = fmaf(m, p2.x, s[4]); s[5] = fmaf(m, p2.y, s[5]);
        s[6] = fmaf(m, pq.x, s[6]); s[7] = fmaf(m, pq.y, s[7]);
        s[8] += m;
    }
#pragma unroll
    for (int k = 0; k < 9; k++)
#pragma unroll
        for (int o = 16; o > 0; o >>= 1)
            s[k] += __shfl_down_sync(0xffffffffu, s[k], o);
    if (lane == 0)
#pragma unroll
        for (int k = 0; k < 9; k++) s_red[warp][k] = s[k];
    __syncthreads();
    if (tid == 0) {
        float t[9] = {0, 0, 0, 0, 0, 0, 0, 0, 0};
        for (int w = 0; w < 8; w++)
            for (int k = 0; k < 9; k++) t[k] += s_red[w][k];
        s_hdr[0] = pack2(t[0], t[1]);
        s_hdr[1] = pack2(t[2], t[3]);
        s_hdr[2] = pack2(t[4], t[5]);
        s_hdr[3] = pack2(t[6], t[7]);
        s_nvf = t[8];
    }
    __syncthreads();

    const int cg = tid & (NCG - 1);
    const int rg = tid >> 4;
    const int row0 = tile * ROWS_PER_CTA + rg * RPT;

    // ---- hot-loop register set: coefficients + accumulators only ----
    u64 a0[RPT], a1[RPT], a2[RPT], cr[RPT];
    float accS[RPT] = {0.0f, 0.0f, 0.0f, 0.0f};
#pragma unroll
    for (int r = 0; r < RPT; r++) {
        ulonglong2 qA = sA[row0 + r];
        ulonglong2 qB = sB[row0 + r];
        a0[r] = mul2(qA.x, NEG2_PACKED);
        a1[r] = mul2(qA.y, NEG2_PACKED);
        a2[r] = mul2(qB.x, NEG2_PACKED);
        cr[r] = qB.y;
    }
    float anyrow = smsk[row0] + smsk[row0 + 1] + smsk[row0 + 2] + smsk[row0 + 3];

    if (anyrow != 0.0f) {
#pragma unroll 8
        for (int k = cg; k < LN; k += NCG) {
            ulonglong2 qA = sA[k];
            ulonglong2 qB = sB[k];
            float mj = smsk[k];
#pragma unroll
            for (int r = 0; r < RPT; r++) {
                u64 t = fma2(a0[r], qA.x, cr[r]);
                t = fma2(a1[r], qA.y, t);
                t = fma2(a2[r], qB.x, t);
                t = add2(t, qB.y);
                float2 d = unpack2(t);               // (d2x, d2y)
                float prod = fmaxf(d.x * d.y, 0.0f);
                accS[r] = fmaf(mj, fast_sqrt(prod), accS[r]);  // masked dx*dy
            }
        }
    }

    // ---- post-loop: closed-form row terms (constants reloaded from smem) ----
    float tsum = 0.0f;
    {
        const u64 S0 = s_hdr[0], S1 = s_hdr[1], S2 = s_hdr[2], SQ = s_hdr[3];
        const u64 NV2 = pack2(s_nvf, s_nvf);
#pragma unroll
        for (int r = 0; r < RPT; r++) {
            ulonglong2 qA = sA[row0 + r];
            ulonglong2 qB = sB[row0 + r];
            // Sum_j mj*d2(i,j) = nv*sq_i + SQsum - 2 * p_i . S   (packed x/y)
            u64 dot = fma2(qA.x, S0, fma2(qA.y, S1, mul2(qB.x, S2)));
            u64 Cr  = fma2(dot, NEG2_PACKED, fma2(qB.y, NV2, SQ));
            float2 c = unpack2(Cr);
            float v = -2.0f * accS[r];
            if (cg == 0) v += (c.x + c.y);          // crTot exactly once per row
            tsum = fmaf(smsk[row0 + r], v, tsum);   // row mask outside
        }
    }

    // ---- deterministic block reduce ----
#pragma unroll
    for (int o = 16; o > 0; o >>= 1)
        tsum += __shfl_down_sync(0xffffffffu, tsum, o);
    if ((tid & 31) == 0) wsum[tid >> 5] = tsum;
    __syncthreads();
    if (tid == 0) {
        float v = 0.0f;
        for (int w = 0; w < 8; w++) v += wsum[w];
        g_part[b * TILES + tile] = v;
        __threadfence();
        int old = atomicAdd(&g_ctr, 1);
        s_last = (old == TOTAL_CTAS - 1) ? 1 : 0;
    }
    __syncthreads();

    // ---- last CTA: fused final reduction (deterministic fixed-order reads) ----
    if (s_last) {
        float v = 0.0f;
        if (tid < BATCH) {
            float ssum = 0.0f;
            for (int t = 0; t < TILES; t++)
                ssum += __ldcg(&g_part[tid * TILES + t]);
            v = fast_sqrt(fmaxf(ssum, 0.0f));
        }
#pragma unroll
        for (int o = 16; o > 0; o >>= 1)
            v += __shfl_down_sync(0xffffffffu, v, o);
        if ((tid & 31) == 0) wsum[tid >> 5] = v;
        __syncthreads();
        if (tid == 0) {
            const float denom = 723.3699523f;  // sqrt(1024^2/2 - 1024)
            out[0] = (wsum[0] + wsum[1]) / denom / (float)BATCH;
            g_ctr = 0;                          // reset for next graph replay
        }
    }
}

extern "C" void kernel_launch(void* const* d_in, const int* in_sizes, int n_in,
                              void* d_out, int out_size) {
    const float* x = (const float*)d_in[0];
    const float* y = (const float*)d_in[1];
    float* out = (float*)d_out;
    (void)in_sizes; (void)n_in; (void)out_size;

    pre_kernel<<<LN / 4, THREADS>>>(x, y);
    dim3 grid(BATCH, TILES);
    pair_kernel<<<grid, THREADS>>>(out);
}

// round 7
// speedup vs baseline: 2.2137x; 2.2137x over previous
#include <cuda_runtime.h>

#define LN 1024
#define BATCH 64
#define THREADS 256
#define NCG 16
#define RPT 4
#define ROWS_PER_CTA 64
#define TILES (LN / ROWS_PER_CTA)
#define TOTAL_CTAS (BATCH * TILES)

typedef unsigned long long u64;

// Scratch (device globals; no runtime allocation).
__device__ ulonglong2 g_colA[BATCH][LN];  // ( pack(x0,y0), pack(x1,y1) )
__device__ ulonglong2 g_colB[BATCH][LN];  // ( pack(x2,y2), pack(sqx,sqy) )
__device__ float      g_msk[BATCH][LN];   // 1.0 if y-row observed else 0.0
__device__ u64        g_hdr[BATCH][4];    // S0,S1,S2,SQ packed masked sums
__device__ float      g_nvf[BATCH];
__device__ float      g_part[TOTAL_CTAS];
__device__ int        g_ctr = 0;

// ---------- f32x2 helpers ----------
__device__ __forceinline__ u64 fma2(u64 a, u64 b, u64 c) {
    u64 d; asm("fma.rn.f32x2 %0, %1, %2, %3;" : "=l"(d) : "l"(a), "l"(b), "l"(c)); return d;
}
__device__ __forceinline__ u64 add2(u64 a, u64 b) {
    u64 d; asm("add.rn.f32x2 %0, %1, %2;" : "=l"(d) : "l"(a), "l"(b)); return d;
}
__device__ __forceinline__ u64 mul2(u64 a, u64 b) {
    u64 d; asm("mul.rn.f32x2 %0, %1, %2;" : "=l"(d) : "l"(a), "l"(b)); return d;
}
__device__ __forceinline__ u64 pack2(float lo, float hi) {
    u64 d; asm("mov.b64 %0, {%1, %2};" : "=l"(d) : "f"(lo), "f"(hi)); return d;
}
__device__ __forceinline__ float2 unpack2(u64 a) {
    float lo, hi; asm("mov.b64 {%0, %1}, %2;" : "=f"(lo), "=f"(hi) : "l"(a));
    return make_float2(lo, hi);
}
__device__ __forceinline__ float fast_sqrt(float a) {
    float r; asm("sqrt.approx.f32 %0, %1;" : "=f"(r) : "f"(a)); return r;
}

#define NEG2_PACKED 0xC0000000C0000000ULL  // (-2.0f, -2.0f)

// ---------- pre-kernel: pure transform, fully coalesced ----------
__global__ __launch_bounds__(THREADS)
void pre_kernel(const float* __restrict__ x, const float* __restrict__ y) {
    const int tid = threadIdx.x;
    const int b  = tid & (BATCH - 1);
    const int dl = tid >> 6;
    const int l  = blockIdx.x * 4 + dl;
    const int base = (l * BATCH + b) * 3;

    float x0 = x[base], x1 = x[base + 1], x2 = x[base + 2];
    float y0 = y[base], y1 = y[base + 1], y2 = y[base + 2];
    float sqx = fmaf(x2, x2, fmaf(x1, x1, x0 * x0));
    float sqy = fmaf(y2, y2, fmaf(y1, y1, y0 * y0));
    float m = ((y0 + y1 + y2) != 0.0f) ? 1.0f : 0.0f;

    ulonglong2 qa, qb;
    qa.x = pack2(x0, y0); qa.y = pack2(x1, y1);
    qb.x = pack2(x2, y2); qb.y = pack2(sqx, sqy);
    g_colA[b][l] = qa;
    g_colB[b][l] = qb;
    g_msk[b][l]  = m;
}

// ---------- header kernel: per-batch masked sums (deterministic) ----------
__global__ __launch_bounds__(THREADS)
void hdr_kernel() {
    const int b = blockIdx.x, tid = threadIdx.x;
    const int warp = tid >> 5, lane = tid & 31;
    __shared__ float s_red[8][9];

    float s[9] = {0, 0, 0, 0, 0, 0, 0, 0, 0};
#pragma unroll
    for (int i = tid; i < LN; i += THREADS) {
        ulonglong2 qa = g_colA[b][i];
        ulonglong2 qb = g_colB[b][i];
        float m = g_msk[b][i];
        float2 p0 = unpack2(qa.x), p1 = unpack2(qa.y);
        float2 p2 = unpack2(qb.x), pq = unpack2(qb.y);
        s[0] = fmaf(m, p0.x, s[0]); s[1] = fmaf(m, p0.y, s[1]);
        s[2] = fmaf(m, p1.x, s[2]); s[3] = fmaf(m, p1.y, s[3]);
        s[4] = fmaf(m, p2.x, s[4]); s[5] = fmaf(m, p2.y, s[5]);
        s[6] = fmaf(m, pq.x, s[6]); s[7] = fmaf(m, pq.y, s[7]);
        s[8] += m;
    }
#pragma unroll
    for (int k = 0; k < 9; k++)
#pragma unroll
        for (int o = 16; o > 0; o >>= 1)
            s[k] += __shfl_down_sync(0xffffffffu, s[k], o);
    if (lane == 0)
#pragma unroll
        for (int k = 0; k < 9; k++) s_red[warp][k] = s[k];
    __syncthreads();
    if (tid == 0) {
        float t[9] = {0, 0, 0, 0, 0, 0, 0, 0, 0};
        for (int w = 0; w < 8; w++)
            for (int k = 0; k < 9; k++) t[k] += s_red[w][k];
        g_hdr[b][0] = pack2(t[0], t[1]);
        g_hdr[b][1] = pack2(t[2], t[3]);
        g_hdr[b][2] = pack2(t[4], t[5]);
        g_hdr[b][3] = pack2(t[6], t[7]);
        g_nvf[b] = t[8];
    }
}

// ---------- pair kernel: triangular (symmetry-halved) cross term ----------
__global__ __launch_bounds__(THREADS, 4)
void pair_kernel(float* __restrict__ out) {
    const int b = blockIdx.x, tile = blockIdx.y, tid = threadIdx.x;
    const int R = tile * ROWS_PER_CTA;

    __shared__ ulonglong2 sA[LN];
    __shared__ ulonglong2 sB[LN];
    __shared__ float smsk[LN];
    __shared__ float wsum[8];
    __shared__ int   s_last;

    // fill only columns [R, LN) — all this CTA touches
    for (int i = R + tid; i < LN; i += THREADS) {
        sA[i] = g_colA[b][i];
        sB[i] = g_colB[b][i];
        smsk[i] = g_msk[b][i];
    }
    __syncthreads();

    const int cg = tid & (NCG - 1);
    const int rg = tid >> 4;
    const int row0 = R + rg * RPT;

    // hot-loop register set: coefficients + accumulators only
    u64 a0[RPT], a1[RPT], a2[RPT], cr[RPT];
    float accD[RPT] = {0, 0, 0, 0};   // diagonal tile, weight 1
    float accU[RPT] = {0, 0, 0, 0};   // strict upper tiles, weight 2
#pragma unroll
    for (int r = 0; r < RPT; r++) {
        ulonglong2 qA = sA[row0 + r];
        ulonglong2 qB = sB[row0 + r];
        a0[r] = mul2(qA.x, NEG2_PACKED);
        a1[r] = mul2(qA.y, NEG2_PACKED);
        a2[r] = mul2(qB.x, NEG2_PACKED);
        cr[r] = qB.y;
    }
    float anyrow = smsk[row0] + smsk[row0 + 1] + smsk[row0 + 2] + smsk[row0 + 3];

    if (anyrow != 0.0f) {
        // diagonal 64-col tile: full (both orders counted once here, incl. k==i ~ 0)
#pragma unroll
        for (int j = 0; j < 4; j++) {
            int k = R + j * NCG + cg;
            ulonglong2 qA = sA[k];
            ulonglong2 qB = sB[k];
            float mj = smsk[k];
#pragma unroll
            for (int r = 0; r < RPT; r++) {
                u64 t = fma2(a0[r], qA.x, cr[r]);
                t = fma2(a1[r], qA.y, t);
                t = fma2(a2[r], qB.x, t);
                t = add2(t, qB.y);
                float2 d = unpack2(t);
                float prod = fmaxf(d.x * d.y, 0.0f);
                accD[r] = fmaf(mj, fast_sqrt(prod), accD[r]);
            }
        }
        // strict upper columns: counted twice by symmetry
#pragma unroll 4
        for (int k = R + ROWS_PER_CTA + cg; k < LN; k += NCG) {
            ulonglong2 qA = sA[k];
            ulonglong2 qB = sB[k];
            float mj = smsk[k];
#pragma unroll
            for (int r = 0; r < RPT; r++) {
                u64 t = fma2(a0[r], qA.x, cr[r]);
                t = fma2(a1[r], qA.y, t);
                t = fma2(a2[r], qB.x, t);
                t = add2(t, qB.y);
                float2 d = unpack2(t);
                float prod = fmaxf(d.x * d.y, 0.0f);
                accU[r] = fmaf(mj, fast_sqrt(prod), accU[r]);
            }
        }
    }

    // post-loop: closed-form row terms (header constants from global, post-loop)
    float tsum = 0.0f;
    {
        const u64 S0 = __ldg(&g_hdr[b][0]);
        const u64 S1 = __ldg(&g_hdr[b][1]);
        const u64 S2 = __ldg(&g_hdr[b][2]);
        const u64 SQ = __ldg(&g_hdr[b][3]);
        const float nvf = __ldg(&g_nvf[b]);
        const u64 NV2 = pack2(nvf, nvf);
#pragma unroll
        for (int r = 0; r < RPT; r++) {
            ulonglong2 qA = sA[row0 + r];
            ulonglong2 qB = sB[row0 + r];
            // Sum_j mj*d2(i,j) = nv*sq_i + SQsum - 2 * p_i . S   (packed x/y)
            u64 dot = fma2(qA.x, S0, fma2(qA.y, S1, mul2(qB.x, S2)));
            u64 Cr  = fma2(dot, NEG2_PACKED, fma2(qB.y, NV2, SQ));
            float2 c = unpack2(Cr);
            float v = -2.0f * fmaf(2.0f, accU[r], accD[r]);
            if (cg == 0) v += (c.x + c.y);          // crTot exactly once per row
            tsum = fmaf(smsk[row0 + r], v, tsum);   // row mask outside
        }
    }

    // deterministic block reduce
#pragma unroll
    for (int o = 16; o > 0; o >>= 1)
        tsum += __shfl_down_sync(0xffffffffu, tsum, o);
    if ((tid & 31) == 0) wsum[tid >> 5] = tsum;
    __syncthreads();
    if (tid == 0) {
        float v = 0.0f;
        for (int w = 0; w < 8; w++) v += wsum[w];
        g_part[b * TILES + tile] = v;
        __threadfence();
        int old = atomicAdd(&g_ctr, 1);
        s_last = (old == TOTAL_CTAS - 1) ? 1 : 0;
    }
    __syncthreads();

    // last CTA: fused final reduction (deterministic fixed-order reads)
    if (s_last) {
        float v = 0.0f;
        if (tid < BATCH) {
            float ssum = 0.0f;
            for (int t = 0; t < TILES; t++)
                ssum += __ldcg(&g_part[tid * TILES + t]);
            v = fast_sqrt(fmaxf(ssum, 0.0f));
        }
#pragma unroll
        for (int o = 16; o > 0; o >>= 1)
            v += __shfl_down_sync(0xffffffffu, v, o);
        if ((tid & 31) == 0) wsum[tid >> 5] = v;
        __syncthreads();
        if (tid == 0) {
            const float denom = 723.3699523f;  // sqrt(1024^2/2 - 1024)
            out[0] = (wsum[0] + wsum[1]) / denom / (float)BATCH;
            g_ctr = 0;                          // reset for next graph replay
        }
    }
}

extern "C" void kernel_launch(void* const* d_in, const int* in_sizes, int n_in,
                              void* d_out, int out_size) {
    const float* x = (const float*)d_in[0];
    const float* y = (const float*)d_in[1];
    float* out = (float*)d_out;
    (void)in_sizes; (void)n_in; (void)out_size;

    pre_kernel<<<LN / 4, THREADS>>>(x, y);
    hdr_kernel<<<BATCH, THREADS>>>();
    dim3 grid(BATCH, TILES);   // y = tile: heavy tiles (t=0) get lowest bids -> launch first
    pair_kernel<<<grid, THREADS>>>(out);
}